// round 5
// baseline (speedup 1.0000x reference)
#include <cuda_runtime.h>
#include <math.h>

#define BATCH 128
#define SEQ   1024
#define INP   7
#define HID   64
#define OUTD  500
#define MTOT  (BATCH*SEQ)   // 131072
#define FTM   128
#define FTN   128
#define HSP   20
#define NLSTM 64            // lstm CTAs, 2 batches each
#define NFC   84            // dedicated fc consumer CTAs
#define GRID  (NLSTM + NFC) // 148 = one wave, 1 CTA/SM

typedef unsigned long long u64;

__device__ float g_hT[(size_t)HID * MTOT];   // h transposed: g_hT[k][b*SEQ+t]
__device__ volatile int g_prog[BATCH];       // lstm progress per batch (zero-init)

// ---- f32x2 packed helpers ----
__device__ __forceinline__ u64 pack2(float a, float b) {
    u64 r;
    asm("mov.b64 %0, {%1, %2};" : "=l"(r)
        : "r"(__float_as_uint(a)), "r"(__float_as_uint(b)));
    return r;
}
__device__ __forceinline__ u64 ffma2(u64 a, u64 b, u64 c) {
    u64 d;
    asm("fma.rn.f32x2 %0, %1, %2, %3;" : "=l"(d) : "l"(a), "l"(b), "l"(c));
    return d;
}
__device__ __forceinline__ u64 fadd2(u64 a, u64 b) {
    u64 d;
    asm("add.rn.f32x2 %0, %1, %2;" : "=l"(d) : "l"(a), "l"(b));
    return d;
}
__device__ __forceinline__ void unpack2(u64 v, float& lo, float& hi) {
    unsigned int l, h;
    asm("mov.b64 {%0, %1}, %2;" : "=r"(l), "=r"(h) : "l"(v));
    lo = __uint_as_float(l); hi = __uint_as_float(h);
}
__device__ __forceinline__ float tanhf_fast(float x) {
    float y;
    asm("tanh.approx.f32 %0, %1;" : "=f"(y) : "f"(x));
    return y;
}

// ---------------------------------------------------------------------------
// FC job: one 128-step window of one batch. out[rows, 500] += A[128,64]@W^T.
// 256 threads, thread tile 16m x 4n, FFMA2 accumulators. Waits on g_prog.
// ---------------------------------------------------------------------------
__device__ void fc_job(char* dynsmem, int b, int w,
                       const float* __restrict__ W_fc,
                       const float* __restrict__ b_fc,
                       float* __restrict__ out)
{
    float (*As)[FTM] = (float(*)[FTM])dynsmem;                      // 32 KB
    float (*Bs)[FTN] = (float(*)[FTN])(dynsmem + HID*FTM*4);        // 32 KB

    const int tid = threadIdx.x;
    const int tx  = tid & 31;
    const int ty  = tid >> 5;
    const int n0  = tx * 4;
    const int m0  = ty * 16;

    if (tid == 0) {
        while (g_prog[b] < (w + 1) * 128) { }   // volatile spin
        __threadfence();                        // acquire
    }
    __syncthreads();

    const int rowbase = b * SEQ + w * FTM;

    for (int nt = 0; nt < 4; ++nt) {
        __syncthreads();   // prior compute done; safe to overwrite tiles
        if (nt == 0) {
            #pragma unroll
            for (int l2 = 0; l2 < 8; ++l2) {
                int fid = tid + l2*256;
                int k   = fid >> 5;
                int m4  = (fid & 31) * 4;
                *(float4*)&As[k][m4] =
                    *(const float4*)(g_hT + (size_t)k*MTOT + rowbase + m4);
            }
        }
        const int col0 = nt * FTN;
        {   // Bs[k][n] = W_fc[col0+n][k]
            int n   = tid >> 1;
            int kf0 = (tid & 1) * 8;
            int r   = col0 + n;
            #pragma unroll
            for (int q = 0; q < 8; ++q) {
                float4 v = make_float4(0.f,0.f,0.f,0.f);
                if (r < OUTD)
                    v = *(const float4*)(W_fc + (size_t)r*HID + (kf0+q)*4);
                int kk = (kf0+q)*4;
                Bs[kk+0][n] = v.x;
                Bs[kk+1][n] = v.y;
                Bs[kk+2][n] = v.z;
                Bs[kk+3][n] = v.w;
            }
        }
        __syncthreads();

        u64 acc[8][4];
        #pragma unroll
        for (int mm = 0; mm < 8; ++mm)
            #pragma unroll
            for (int nn = 0; nn < 4; ++nn) acc[mm][nn] = 0ull;

        const float* asr = &As[0][m0];
        const float* bsr = &Bs[0][n0];
        #pragma unroll 4
        for (int k = 0; k < HID; ++k) {
            ulonglong2 u0 = *(const ulonglong2*)(asr + 0);
            ulonglong2 u1 = *(const ulonglong2*)(asr + 4);
            ulonglong2 u2 = *(const ulonglong2*)(asr + 8);
            ulonglong2 u3 = *(const ulonglong2*)(asr + 12);
            float4 bv = *(const float4*)(bsr);
            asr += FTM; bsr += FTN;
            u64 b2[4];
            b2[0] = pack2(bv.x, bv.x);
            b2[1] = pack2(bv.y, bv.y);
            b2[2] = pack2(bv.z, bv.z);
            b2[3] = pack2(bv.w, bv.w);
            u64 ap[8] = {u0.x,u0.y,u1.x,u1.y,u2.x,u2.y,u3.x,u3.y};
            #pragma unroll
            for (int nn = 0; nn < 4; ++nn) {
                #pragma unroll
                for (int mm = 0; mm < 8; ++mm)
                    acc[mm][nn] = ffma2(ap[mm], b2[nn], acc[mm][nn]);
            }
        }

        if (col0 + n0 < OUTD) {   // 500%4==0: 4-strip all-in/all-out
            float4 bias = *(const float4*)(b_fc + col0 + n0);
            const float bb[4] = {bias.x, bias.y, bias.z, bias.w};
            #pragma unroll
            for (int mm = 0; mm < 8; ++mm) {
                float lo[4], hi[4];
                #pragma unroll
                for (int nn = 0; nn < 4; ++nn) unpack2(acc[mm][nn], lo[nn], hi[nn]);
                int r0 = rowbase + m0 + 2*mm;
                float4 o0, o1;
                o0.x=lo[0]+bb[0]; o0.y=lo[1]+bb[1]; o0.z=lo[2]+bb[2]; o0.w=lo[3]+bb[3];
                o1.x=hi[0]+bb[0]; o1.y=hi[1]+bb[1]; o1.z=hi[2]+bb[2]; o1.w=hi[3]+bb[3];
                *(float4*)(out + (size_t)r0     * OUTD + col0 + n0) = o0;
                *(float4*)(out + (size_t)(r0+1) * OUTD + col0 + n0) = o1;
            }
        }
    }
}

// ---------------------------------------------------------------------------
// Fused spatial-partition kernel: blocks 0..63 = lstm (2 batches each),
// blocks 64..147 = fc consumers. One wave -> 1 CTA/SM, no SM sharing.
// ---------------------------------------------------------------------------
__global__ __launch_bounds__(256, 1)
void fused_kernel(const float* __restrict__ x,
                  const float* __restrict__ W_ih,
                  const float* __restrict__ W_hh,
                  const float* __restrict__ b_ih,
                  const float* __restrict__ b_hh,
                  const float* __restrict__ W_fc,
                  const float* __restrict__ b_fc,
                  float* __restrict__ out)
{
    extern __shared__ char dynsmem[];
    const int bid = blockIdx.x;
    const int tid = threadIdx.x;

    if (bid >= NLSTM) {
        // ---------------- FC consumer role ----------------
        const int i = bid - NLSTM;
        for (int q = i; q < 896; q += NFC)          // windows 0..6, w-major
            fc_job(dynsmem, q & 127, q >> 7, W_fc, b_fc, out);
        if (i < 64)                                  // share of window 7
            fc_job(dynsmem, 64 + i, 7, W_fc, b_fc, out);
        return;
    }

    // ---------------- LSTM role: 2 batches per CTA ----------------
    float* xs     = (float*)dynsmem;                 // [2][SEQ*INP]  57344 B
    float* hb     = xs + 2*SEQ*INP;                  // [2][2][HID]    1024 B
    float* hstage = hb + 2*2*HID;                    // [2][2][HID][HSP] 20480 B

    const int b0   = bid * 2;
    const int hh   = tid >> 2;
    const int gate = tid & 3;
    const int row  = gate * HID + hh;
    const int lane = tid & 31;
    const int lb   = lane & ~3;

    // stage x for both batches (coalesced float4)
    #pragma unroll
    for (int bb = 0; bb < 2; ++bb) {
        const float4* src = (const float4*)(x + (size_t)(b0+bb) * SEQ * INP);
        float4* dst = (float4*)(xs + bb * SEQ * INP);
        #pragma unroll
        for (int i = 0; i < (SEQ*INP)/(4*256); ++i)
            dst[tid + i*256] = src[tid + i*256];
    }

    // W_hh row -> packed registers (shared by both batches)
    u64 w2[HID/2];
    {
        const ulonglong2* wr = (const ulonglong2*)(W_hh + (size_t)row * HID);
        #pragma unroll
        for (int i = 0; i < HID/4; ++i) {
            ulonglong2 v = wr[i];
            w2[2*i+0] = v.x; w2[2*i+1] = v.y;
        }
    }
    float wih[INP];
    #pragma unroll
    for (int i = 0; i < INP; ++i) wih[i] = W_ih[row*INP + i];
    const float bias = b_ih[row] + b_hh[row];

    const float scale = (gate == 2) ? 1.0f : 0.5f;
    const float off   = (gate == 2) ? 0.0f : 0.5f;

    if (tid < 2*HID) hb[((tid >> 6) * 2 + 0) * HID + (tid & 63)] = 0.0f;
    float c[2] = {0.0f, 0.0f};
    __syncthreads();

    float xacc[2];
    #pragma unroll
    for (int bb = 0; bb < 2; ++bb) {
        const float* xt = xs + bb*SEQ*INP;
        float a = bias;
        #pragma unroll
        for (int i = 0; i < INP; ++i) a = fmaf(xt[i], wih[i], a);
        xacc[bb] = a;
    }

    int cur = 0;
    for (int t = 0; t < SEQ; ++t) {
        #pragma unroll
        for (int bb = 0; bb < 2; ++bb) {
            const ulonglong2* hv =
                (const ulonglong2*)(hb + (bb*2 + cur) * HID);
            u64 a[8];
            #pragma unroll
            for (int i = 0; i < 8; ++i) a[i] = 0ull;
            #pragma unroll
            for (int j = 0; j < 4; ++j) {
                ulonglong2 h0 = hv[4*j+0];
                ulonglong2 h1 = hv[4*j+1];
                ulonglong2 h2 = hv[4*j+2];
                ulonglong2 h3 = hv[4*j+3];
                a[0] = ffma2(h0.x, w2[8*j+0], a[0]);
                a[1] = ffma2(h0.y, w2[8*j+1], a[1]);
                a[2] = ffma2(h1.x, w2[8*j+2], a[2]);
                a[3] = ffma2(h1.y, w2[8*j+3], a[3]);
                a[4] = ffma2(h2.x, w2[8*j+4], a[4]);
                a[5] = ffma2(h2.y, w2[8*j+5], a[5]);
                a[6] = ffma2(h3.x, w2[8*j+6], a[6]);
                a[7] = ffma2(h3.y, w2[8*j+7], a[7]);
            }
            u64 s0 = fadd2(a[0], a[1]);
            u64 s1 = fadd2(a[2], a[3]);
            u64 s2 = fadd2(a[4], a[5]);
            u64 s3 = fadd2(a[6], a[7]);
            u64 s  = fadd2(fadd2(s0, s1), fadd2(s2, s3));
            float slo, shi; unpack2(s, slo, shi);
            float pre = xacc[bb] + slo + shi;

            float act = fmaf(scale, tanhf_fast(scale * pre), off);

            float ig = __shfl_sync(0xffffffffu, act, lb+0);
            float fg = __shfl_sync(0xffffffffu, act, lb+1);
            float gg = __shfl_sync(0xffffffffu, act, lb+2);
            float og = __shfl_sync(0xffffffffu, act, lb+3);

            c[bb] = fmaf(fg, c[bb], ig*gg);
            float h = og * tanhf_fast(c[bb]);
            if (gate == 0) {
                hb[(bb*2 + (cur^1)) * HID + hh] = h;
                hstage[((bb*2 + ((t>>4)&1)) * HID + hh) * HSP + (t & 15)] = h;
            }

            // next-step x contribution (off critical path)
            int tn = (t + 1 < SEQ) ? t + 1 : 0;
            const float* xt = xs + bb*SEQ*INP + tn*INP;
            float xn = bias;
            #pragma unroll
            for (int i = 0; i < INP; ++i) xn = fmaf(xt[i], wih[i], xn);
            xacc[bb] = xn;
        }

        __syncthreads();
        cur ^= 1;

        if ((t & 15) == 15) {
            int wsel = (t >> 4) & 1;
            int k = tid >> 2;
            int j = (tid & 3) * 4;
            #pragma unroll
            for (int bb = 0; bb < 2; ++bb) {
                const float* hp = &hstage[((bb*2 + wsel) * HID + k) * HSP + j];
                float4 v = make_float4(hp[0], hp[1], hp[2], hp[3]);
                *(float4*)(g_hT + (size_t)k*MTOT + (size_t)(b0+bb)*SEQ + (t-15) + j) = v;
            }
            __threadfence();   // dumps visible before next flag publish
        } else if ((t & 15) == 0 && t != 0) {
            // prev window's dump+fence ordered before this point by the barrier
            if (tid < 2) g_prog[b0 + tid] = t;
        }
    }

    __syncthreads();                 // all final dumps + fences done
    if (tid < 2) g_prog[b0 + tid] = SEQ;
    __syncthreads();

    // tail: this CTA computes the FC for window 7 of batch b0+? (b==bid here)
    fc_job(dynsmem, bid, 7, W_fc, b_fc, out);
}

extern "C" void kernel_launch(void* const* d_in, const int* in_sizes, int n_in,
                              void* d_out, int out_size)
{
    const float* x    = (const float*)d_in[0];
    const float* W_ih = (const float*)d_in[1];
    const float* W_hh = (const float*)d_in[2];
    const float* b_ih = (const float*)d_in[3];
    const float* b_hh = (const float*)d_in[4];
    const float* W_fc = (const float*)d_in[5];
    const float* b_fc = (const float*)d_in[6];
    float* out = (float*)d_out;

    static int smem_set = 0;
    const int dyn = 80 * 1024;       // lstm 78.8 KB / fc 64 KB
    if (!smem_set) {
        cudaFuncSetAttribute(fused_kernel,
                             cudaFuncAttributeMaxDynamicSharedMemorySize, dyn);
        smem_set = 1;
    }
    fused_kernel<<<GRID, 256, dyn>>>(x, W_ih, W_hh, b_ih, b_hh, W_fc, b_fc, out);
}

// round 6
// speedup vs baseline: 1.0764x; 1.0764x over previous
#include <cuda_runtime.h>
#include <math.h>

#define BATCH 128
#define SEQ   1024
#define INP   7
#define HID   64
#define OUTD  500
#define MTOT  (BATCH*SEQ)   // 131072
#define FTM   128
#define FTN   128
#define HSP   20
#define NLSTM 64            // lstm CTAs, 2 batches each (warp-split)
#define NFC   84            // dedicated fc consumer CTAs
#define GRID  (NLSTM + NFC) // 148 = one wave, 1 CTA/SM
#define NTHR  512

typedef unsigned long long u64;

__device__ float g_hT[(size_t)HID * MTOT];   // h transposed: g_hT[k][b*SEQ+t]
__device__ volatile int g_prog[BATCH];       // lstm progress per batch (zero-init)

// ---- f32x2 packed helpers ----
__device__ __forceinline__ u64 pack2(float a, float b) {
    u64 r;
    asm("mov.b64 %0, {%1, %2};" : "=l"(r)
        : "r"(__float_as_uint(a)), "r"(__float_as_uint(b)));
    return r;
}
__device__ __forceinline__ u64 ffma2(u64 a, u64 b, u64 c) {
    u64 d;
    asm("fma.rn.f32x2 %0, %1, %2, %3;" : "=l"(d) : "l"(a), "l"(b), "l"(c));
    return d;
}
__device__ __forceinline__ u64 fadd2(u64 a, u64 b) {
    u64 d;
    asm("add.rn.f32x2 %0, %1, %2;" : "=l"(d) : "l"(a), "l"(b));
    return d;
}
__device__ __forceinline__ void unpack2(u64 v, float& lo, float& hi) {
    unsigned int l, h;
    asm("mov.b64 {%0, %1}, %2;" : "=r"(l), "=r"(h) : "l"(v));
    lo = __uint_as_float(l); hi = __uint_as_float(h);
}
__device__ __forceinline__ float tanhf_fast(float x) {
    float y;
    asm("tanh.approx.f32 %0, %1;" : "=f"(y) : "f"(x));
    return y;
}

// ---------------------------------------------------------------------------
// FC job: one 128-step window of one batch. 512 threads, thread tile 8m x 4n.
// Waits on g_prog[b] before consuming g_hT.
// ---------------------------------------------------------------------------
__device__ void fc_job(char* dynsmem, int b, int w,
                       const float* __restrict__ W_fc,
                       const float* __restrict__ b_fc,
                       float* __restrict__ out)
{
    float (*As)[FTM] = (float(*)[FTM])dynsmem;                      // 32 KB
    float (*Bs)[FTN] = (float(*)[FTN])(dynsmem + HID*FTM*4);        // 32 KB

    const int tid = threadIdx.x;
    const int tx  = tid & 31;
    const int ty  = tid >> 5;            // 0..15
    const int n0  = tx * 4;
    const int m0  = ty * 8;

    if (tid == 0) {
        while (g_prog[b] < (w + 1) * 128) { }   // volatile spin
        __threadfence();                        // acquire
    }
    __syncthreads();

    const int rowbase = b * SEQ + w * FTM;

    for (int nt = 0; nt < 4; ++nt) {
        __syncthreads();   // prior compute done; safe to overwrite tiles
        if (nt == 0) {
            #pragma unroll
            for (int l2 = 0; l2 < 4; ++l2) {
                int fid = tid + l2*NTHR;
                int k   = fid >> 5;
                int m4  = (fid & 31) * 4;
                *(float4*)&As[k][m4] =
                    *(const float4*)(g_hT + (size_t)k*MTOT + rowbase + m4);
            }
        }
        const int col0 = nt * FTN;
        {   // Bs[k][n] = W_fc[col0+n][k] ; 4 threads per n row
            int n   = tid >> 2;              // 0..127
            int kq  = tid & 3;
            int r   = col0 + n;
            #pragma unroll
            for (int q = 0; q < 4; ++q) {
                int kf = kq + q*4;           // 0..15
                float4 v = make_float4(0.f,0.f,0.f,0.f);
                if (r < OUTD)
                    v = *(const float4*)(W_fc + (size_t)r*HID + kf*4);
                int kk = kf*4;
                Bs[kk+0][n] = v.x;
                Bs[kk+1][n] = v.y;
                Bs[kk+2][n] = v.z;
                Bs[kk+3][n] = v.w;
            }
        }
        __syncthreads();

        u64 acc[4][4];
        #pragma unroll
        for (int mm = 0; mm < 4; ++mm)
            #pragma unroll
            for (int nn = 0; nn < 4; ++nn) acc[mm][nn] = 0ull;

        const float* asr = &As[0][m0];
        const float* bsr = &Bs[0][n0];
        #pragma unroll 8
        for (int k = 0; k < HID; ++k) {
            ulonglong2 aA = *(const ulonglong2*)(asr);
            ulonglong2 aB = *(const ulonglong2*)(asr + 4);
            float4 bv = *(const float4*)(bsr);
            asr += FTM; bsr += FTN;
            u64 b2[4];
            b2[0] = pack2(bv.x, bv.x);
            b2[1] = pack2(bv.y, bv.y);
            b2[2] = pack2(bv.z, bv.z);
            b2[3] = pack2(bv.w, bv.w);
            #pragma unroll
            for (int nn = 0; nn < 4; ++nn) {
                acc[0][nn] = ffma2(aA.x, b2[nn], acc[0][nn]);
                acc[1][nn] = ffma2(aA.y, b2[nn], acc[1][nn]);
                acc[2][nn] = ffma2(aB.x, b2[nn], acc[2][nn]);
                acc[3][nn] = ffma2(aB.y, b2[nn], acc[3][nn]);
            }
        }

        if (col0 + n0 < OUTD) {   // 500%4==0: 4-strip all-in/all-out
            float4 bias = *(const float4*)(b_fc + col0 + n0);
            const float bb[4] = {bias.x, bias.y, bias.z, bias.w};
            #pragma unroll
            for (int mm = 0; mm < 4; ++mm) {
                float lo[4], hi[4];
                #pragma unroll
                for (int nn = 0; nn < 4; ++nn) unpack2(acc[mm][nn], lo[nn], hi[nn]);
                int r0 = rowbase + m0 + 2*mm;
                float4 o0, o1;
                o0.x=lo[0]+bb[0]; o0.y=lo[1]+bb[1]; o0.z=lo[2]+bb[2]; o0.w=lo[3]+bb[3];
                o1.x=hi[0]+bb[0]; o1.y=hi[1]+bb[1]; o1.z=hi[2]+bb[2]; o1.w=hi[3]+bb[3];
                *(float4*)(out + (size_t)r0     * OUTD + col0 + n0) = o0;
                *(float4*)(out + (size_t)(r0+1) * OUTD + col0 + n0) = o1;
            }
        }
    }
}

// ---------------------------------------------------------------------------
// Fused kernel: blocks 0..63 = lstm with 2 batches per CTA (warps 0-7 batch
// 2i, warps 8-15 batch 2i+1; each thread does exactly one gate-row, round-3
// per-thread workload). Blocks 64..147 = fc consumers for windows 0..6.
// Window 7 computed by lstm CTAs after the recurrence ends.
// ---------------------------------------------------------------------------
__global__ __launch_bounds__(NTHR, 1)
void fused_kernel(const float* __restrict__ x,
                  const float* __restrict__ W_ih,
                  const float* __restrict__ W_hh,
                  const float* __restrict__ b_ih,
                  const float* __restrict__ b_hh,
                  const float* __restrict__ W_fc,
                  const float* __restrict__ b_fc,
                  float* __restrict__ out)
{
    extern __shared__ char dynsmem[];
    const int bid = blockIdx.x;
    const int tid = threadIdx.x;

    if (bid >= NLSTM) {
        // ---------------- FC consumer role: windows 0..6 ----------------
        const int i = bid - NLSTM;
        for (int q = i; q < 896; q += NFC)          // w-major over windows 0..6
            fc_job(dynsmem, q & 127, q >> 7, W_fc, b_fc, out);
        return;
    }

    // ---------------- LSTM role: warp-split, 2 batches ----------------
    float* xs     = (float*)dynsmem;                 // [2][SEQ*INP]  57344 B
    float* hb     = xs + 2*SEQ*INP;                  // [2][2][HID]    2048 B
    float* hstage = hb + 2*2*HID;                    // [2][2][HID][HSP] 20480 B

    const int b0   = bid * 2;
    const int wg   = tid >> 8;          // 0/1: which batch this warp serves
    const int wtid = tid & 255;         // round-3 thread id within the half
    const int b    = b0 + wg;
    const int hh   = wtid >> 2;
    const int gate = wtid & 3;
    const int row  = gate * HID + hh;
    const int lane = tid & 31;
    const int lb   = lane & ~3;

    // stage x for both batches (rows b0,b0+1 are contiguous in gmem)
    {
        const float4* src = (const float4*)(x + (size_t)b0 * SEQ * INP);
        float4* dst = (float4*)xs;
        #pragma unroll
        for (int i = 0; i < (2*SEQ*INP)/(4*NTHR); ++i)   // 7 iters
            dst[tid + i*NTHR] = src[tid + i*NTHR];
    }

    // W_hh row -> packed registers (64 regs)
    u64 w2[HID/2];
    {
        const ulonglong2* wr = (const ulonglong2*)(W_hh + (size_t)row * HID);
        #pragma unroll
        for (int i = 0; i < HID/4; ++i) {
            ulonglong2 v = wr[i];
            w2[2*i+0] = v.x; w2[2*i+1] = v.y;
        }
    }
    float wih[INP];
    #pragma unroll
    for (int i = 0; i < INP; ++i) wih[i] = W_ih[row*INP + i];
    const float bias = b_ih[row] + b_hh[row];

    const float scale = (gate == 2) ? 1.0f : 0.5f;
    const float off   = (gate == 2) ? 0.0f : 0.5f;

    if (wtid < HID) hb[(wg*2 + 0)*HID + wtid] = 0.0f;
    float c = 0.0f;
    __syncthreads();

    const float* xsb = xs + wg * SEQ * INP;
    float xacc = bias;
    #pragma unroll
    for (int i = 0; i < INP; ++i) xacc = fmaf(xsb[i], wih[i], xacc);

    int cur = 0;
    for (int t = 0; t < SEQ; ++t) {
        // h(t-1) @ W_hh^T : 8 FFMA2 chains of depth 4 (round-3 layout)
        const ulonglong2* hv = (const ulonglong2*)(hb + (wg*2 + cur)*HID);
        u64 a[8];
        #pragma unroll
        for (int i = 0; i < 8; ++i) a[i] = 0ull;
        #pragma unroll
        for (int j = 0; j < 4; ++j) {
            ulonglong2 h0 = hv[4*j+0];
            ulonglong2 h1 = hv[4*j+1];
            ulonglong2 h2 = hv[4*j+2];
            ulonglong2 h3 = hv[4*j+3];
            a[0] = ffma2(h0.x, w2[8*j+0], a[0]);
            a[1] = ffma2(h0.y, w2[8*j+1], a[1]);
            a[2] = ffma2(h1.x, w2[8*j+2], a[2]);
            a[3] = ffma2(h1.y, w2[8*j+3], a[3]);
            a[4] = ffma2(h2.x, w2[8*j+4], a[4]);
            a[5] = ffma2(h2.y, w2[8*j+5], a[5]);
            a[6] = ffma2(h3.x, w2[8*j+6], a[6]);
            a[7] = ffma2(h3.y, w2[8*j+7], a[7]);
        }
        u64 s0 = fadd2(a[0], a[1]);
        u64 s1 = fadd2(a[2], a[3]);
        u64 s2 = fadd2(a[4], a[5]);
        u64 s3 = fadd2(a[6], a[7]);
        u64 s  = fadd2(fadd2(s0, s1), fadd2(s2, s3));
        float slo, shi; unpack2(s, slo, shi);
        float pre = xacc + slo + shi;

        float act = fmaf(scale, tanhf_fast(scale * pre), off);

        float ig = __shfl_sync(0xffffffffu, act, lb+0);
        float fg = __shfl_sync(0xffffffffu, act, lb+1);
        float gg = __shfl_sync(0xffffffffu, act, lb+2);
        float og = __shfl_sync(0xffffffffu, act, lb+3);

        c = fmaf(fg, c, ig*gg);
        float h = og * tanhf_fast(c);
        if (gate == 0) {
            hb[(wg*2 + (cur^1))*HID + hh] = h;
            hstage[((wg*2 + ((t>>4)&1))*HID + hh)*HSP + (t & 15)] = h;
        }

        // next-step x contribution (independent of h; interleaved by compiler)
        int tn = (t + 1 < SEQ) ? t + 1 : 0;
        const float* xt = xsb + tn*INP;
        float xn = bias;
        #pragma unroll
        for (int i = 0; i < INP; ++i) xn = fmaf(xt[i], wih[i], xn);
        xacc = xn;

        __syncthreads();
        cur ^= 1;

        if ((t & 15) == 15) {
            // coalesced dump of completed 16-step window (own batch)
            int wsel = (t >> 4) & 1;
            int k = wtid >> 2;
            int j = (wtid & 3) * 4;
            const float* hp = &hstage[((wg*2 + wsel)*HID + k)*HSP + j];
            float4 v = make_float4(hp[0], hp[1], hp[2], hp[3]);
            *(float4*)(g_hT + (size_t)k*MTOT + (size_t)b*SEQ + (t-15) + j) = v;
            __threadfence();   // dump visible before next flag publish
        } else if ((t & 15) == 0 && t != 0) {
            // prev window's dump+fence ordered before this by the barrier
            if (wtid == 0) g_prog[b] = t;
        }
    }

    __syncthreads();                 // all final dumps + fences done
    if (wtid == 0) g_prog[b] = SEQ;
    __syncthreads();

    // tail: window 7 for this CTA's own two batches (flags already SEQ)
    fc_job(dynsmem, b0,     7, W_fc, b_fc, out);
    fc_job(dynsmem, b0 + 1, 7, W_fc, b_fc, out);
}

extern "C" void kernel_launch(void* const* d_in, const int* in_sizes, int n_in,
                              void* d_out, int out_size)
{
    const float* x    = (const float*)d_in[0];
    const float* W_ih = (const float*)d_in[1];
    const float* W_hh = (const float*)d_in[2];
    const float* b_ih = (const float*)d_in[3];
    const float* b_hh = (const float*)d_in[4];
    const float* W_fc = (const float*)d_in[5];
    const float* b_fc = (const float*)d_in[6];
    float* out = (float*)d_out;

    static int smem_set = 0;
    const int dyn = 80 * 1024;       // lstm 78 KB / fc 64 KB
    if (!smem_set) {
        cudaFuncSetAttribute(fused_kernel,
                             cudaFuncAttributeMaxDynamicSharedMemorySize, dyn);
        smem_set = 1;
    }
    fused_kernel<<<GRID, NTHR, dyn>>>(x, W_ih, W_hh, b_ih, b_hh, W_fc, b_fc, out);
}